// round 7
// baseline (speedup 1.0000x reference)
#include <cuda_runtime.h>
#include <cuda_fp16.h>
#include <cstdint>

// ================= problem constants =================
#define FDIM 512
#define EMAX 256
#define X_SCALE 256.0f
#define W_SCALE 4096.0f
#define B_SCALE (X_SCALE * W_SCALE)
// certified bound: |x·w - xh·wh| <= ERR_COEF * ||x|| * ||w|| (validated R5/R6, rel_err 0.0)
#define ERR_COEF 0.0013f

// ================= device scratch ====================
__device__ int    g_nactive;
__device__ int    g_npass;
__device__ int    g_eidx[EMAX];
__device__ float  g_ta[EMAX];
__device__ float  g_bias_s[EMAX];
__device__ float  g_borig[EMAX];
__device__ float  g_wnorm_s[EMAX];
__device__ __half g_Wh[EMAX * FDIM];

// ================= PTX helpers =======================
__device__ __forceinline__ uint32_t smem_u32(const void* p) {
    uint32_t a;
    asm("{ .reg .u64 t; cvta.to.shared.u64 t, %1; cvt.u32.u64 %0, t; }" : "=r"(a) : "l"(p));
    return a;
}
__device__ __forceinline__ void mma16816(float* c, const uint32_t* a, const uint32_t* b) {
    asm volatile(
        "mma.sync.aligned.m16n8k16.row.col.f32.f16.f16.f32 "
        "{%0,%1,%2,%3}, {%4,%5,%6,%7}, {%8,%9}, {%0,%1,%2,%3};"
        : "+f"(c[0]), "+f"(c[1]), "+f"(c[2]), "+f"(c[3])
        : "r"(a[0]), "r"(a[1]), "r"(a[2]), "r"(a[3]), "r"(b[0]), "r"(b[1]));
}
__device__ __forceinline__ uint32_t pkh2(float a, float b) {
    __half2 h = __floats2half2_rn(a, b);
    return *reinterpret_cast<uint32_t*>(&h);
}

// ============================================================
// Prep: compaction + scaled-fp16 W hi + per-estimator norms.
// (unchanged, validated)
// ============================================================
__global__ __launch_bounds__(256) void pack_kernel(const float* __restrict__ W,
                                                   const float* __restrict__ bias,
                                                   const float* __restrict__ alphas,
                                                   int E) {
    __shared__ int   s_eidx[EMAX];
    __shared__ float s_ta[EMAX];
    __shared__ float s_b[EMAX];
    __shared__ int   wtot[8], woff[8];
    __shared__ int   s_na;
    __shared__ float s_red[8];

    int e = threadIdx.x;
    float ta = 0.f, bi = 0.f;
    int flag = 0;
    if (e < E) {
        ta = truncf(alphas[e]);
        bi = bias[e];
        flag = (ta != 0.f) ? 1 : 0;
    }
    unsigned mask = __ballot_sync(0xffffffffu, flag);
    int lane = e & 31, warp = e >> 5;
    int prefix = __popc(mask & ((1u << lane) - 1u));
    if (lane == 0) wtot[warp] = __popc(mask);
    s_eidx[e] = 0; s_ta[e] = 0.f; s_b[e] = 0.f;
    __syncthreads();
    if (e == 0) {
        int s = 0;
        for (int i = 0; i < 8; i++) { woff[i] = s; s += wtot[i]; }
        s_na = s;
    }
    __syncthreads();
    if (flag) {
        int pos = woff[warp] + prefix;
        s_eidx[pos] = e;
        s_ta[pos] = ta;
        s_b[pos] = bi;
    }
    __syncthreads();

    int na = s_na;
    if (blockIdx.x == 0) {
        g_ta[e]     = s_ta[e];
        g_bias_s[e] = s_b[e] * B_SCALE;
        g_borig[e]  = s_b[e];
        g_eidx[e]   = s_eidx[e];
        if (e == 0) {
            g_nactive = na;
            int np = (na + 127) / 128;
            if (np < 1) np = 1;
            g_npass = np;
        }
    }

    int p = blockIdx.x, t = threadIdx.x;
    float part = 0.f;
    if (p < na) {
        int src = s_eidx[p];
        float2 v = *reinterpret_cast<const float2*>(W + (size_t)src * FDIM + 2 * t);
        float s0 = v.x * W_SCALE, s1 = v.y * W_SCALE;
        *reinterpret_cast<__half2*>(g_Wh + (size_t)p * FDIM + 2 * t) = __floats2half2_rn(s0, s1);
        part = s0 * s0 + s1 * s1;
    } else {
        *reinterpret_cast<__half2*>(g_Wh + (size_t)p * FDIM + 2 * t) = __floats2half2_rn(0.f, 0.f);
    }
#pragma unroll
    for (int o = 16; o; o >>= 1) part += __shfl_xor_sync(0xffffffffu, part, o);
    if (lane == 0) s_red[warp] = part;
    __syncthreads();
    if (t == 0) {
        float s = 0.f;
        for (int i = 0; i < 8; i++) s += s_red[i];
        g_wnorm_s[p] = sqrtf(s);
    }
}

// ============================================================
// Main: 128 rows/CTA. W resident in smem (whole K); A operand loaded
// warp-privately from global straight into registers (NO mainloop barriers).
// 8 warps = 4(M) x 2(N); warp tile m32 x n64.
// ============================================================
#define WSTR 520                       // smem W row stride in halves (conflict-free)
#define OFF_W     0
#define WBYTES    (128 * WSTR * 2)     // 133120
#define OFF_VOTES WBYTES
#define OFF_SBIAS (OFF_VOTES + 512)
#define OFF_STA   (OFF_SBIAS + 512)
#define OFF_SWN   (OFF_STA + 512)
#define OFF_SBO   (OFF_SWN + 512)
#define OFF_SEID  (OFF_SBO + 512)
#define OFF_WL    (OFF_SEID + 512)
#define WLCAP     4096
#define OFF_CNT   (OFF_WL + WLCAP * 4)
#define SMEM_BYTES (OFF_CNT + 32)

__global__ __launch_bounds__(256, 1) void main_kernel(const float* __restrict__ x,
                                                      const float* __restrict__ Wg,
                                                      float* __restrict__ out,
                                                      int N) {
    extern __shared__ char sm[];
    __half* ws   = reinterpret_cast<__half*>(sm + OFF_W);
    float* votes = reinterpret_cast<float*>(sm + OFF_VOTES);
    float* sbias = reinterpret_cast<float*>(sm + OFF_SBIAS);
    float* sta   = reinterpret_cast<float*>(sm + OFF_STA);
    float* swn   = reinterpret_cast<float*>(sm + OFF_SWN);
    float* sbo   = reinterpret_cast<float*>(sm + OFF_SBO);
    int*   seid  = reinterpret_cast<int*>(sm + OFF_SEID);
    int*   wl    = reinterpret_cast<int*>(sm + OFF_WL);
    int*   pcnt  = reinterpret_cast<int*>(sm + OFF_CNT);

    const int tid = threadIdx.x, lane = tid & 31, w = tid >> 5;
    const int l4 = lane >> 2, lm = lane & 3;
    const int mwarp = w & 3, nwarp = w >> 2;
    const int mbase = mwarp * 32, nbase = nwarp * 64;
    const int rowBase = blockIdx.x * 128;   // N == 131072 = 1024*128, exact

    if (tid < 128) votes[tid] = 0.f;
    const int na = g_nactive, npass = g_npass;

    // warp-private x base: this thread's A-fragment home column
    const float* xptr = x + (size_t)(rowBase + mbase + l4) * FDIM + 2 * lm;

    for (int pass = 0; pass < npass; pass++) {
        if (tid < 128) {
            int e = pass * 128 + tid;
            sbias[tid] = g_bias_s[e];
            sta[tid]   = g_ta[e];
            swn[tid]   = g_wnorm_s[e];
            sbo[tid]   = g_borig[e];
            seid[tid]  = g_eidx[e];
        }
        if (tid == 0) *pcnt = 0;

        // ---- load whole W slice [128 x 512 halves] into smem ----
        {
            int row = tid >> 1, half = tid & 1;
            const uint4* src = reinterpret_cast<const uint4*>(
                g_Wh + (size_t)(pass * 128 + row) * FDIM + half * 256);
            uint4* dst = reinterpret_cast<uint4*>(ws + row * WSTR + half * 256);
#pragma unroll
            for (int j = 0; j < 32; j++) dst[j] = src[j];
        }
        __syncthreads();   // ws + pass consts visible; last pass's fixup done

        int pact = na - pass * 128;
        if (pact > 128) pact = 128;
        if (pact < 0) pact = 0;

        float c[2][8][4];
#pragma unroll
        for (int mi = 0; mi < 2; mi++)
#pragma unroll
            for (int ni = 0; ni < 8; ni++)
#pragma unroll
                for (int j = 0; j < 4; j++) c[mi][ni][j] = 0.f;

        float xn4[4] = {0.f, 0.f, 0.f, 0.f};

        // ============ barrier-free mainloop ============
#pragma unroll
        for (int kc = 0; kc < 8; kc++) {
#pragma unroll
            for (int ks = 0; ks < 4; ks++) {
                const int k0 = kc * 64 + ks * 16;
                // load this thread's A-fragment x values (8 floats x 4 rows? -> 4 rows x 4 floats)
                float2 xv[4][2];
#pragma unroll
                for (int r4 = 0; r4 < 4; r4++) {
                    xv[r4][0] = *reinterpret_cast<const float2*>(xptr + (size_t)(r4 * 8) * FDIM + k0);
                    xv[r4][1] = *reinterpret_cast<const float2*>(xptr + (size_t)(r4 * 8) * FDIM + k0 + 8);
                }
                // norms (raw x^2; scaled at epilogue)
#pragma unroll
                for (int r4 = 0; r4 < 4; r4++)
                    xn4[r4] += xv[r4][0].x * xv[r4][0].x + xv[r4][0].y * xv[r4][0].y
                             + xv[r4][1].x * xv[r4][1].x + xv[r4][1].y * xv[r4][1].y;
                // convert to fp16 A fragments
                uint32_t a[2][4];
#pragma unroll
                for (int mi = 0; mi < 2; mi++) {
                    a[mi][0] = pkh2(xv[2 * mi][0].x * X_SCALE,     xv[2 * mi][0].y * X_SCALE);
                    a[mi][1] = pkh2(xv[2 * mi + 1][0].x * X_SCALE, xv[2 * mi + 1][0].y * X_SCALE);
                    a[mi][2] = pkh2(xv[2 * mi][1].x * X_SCALE,     xv[2 * mi][1].y * X_SCALE);
                    a[mi][3] = pkh2(xv[2 * mi + 1][1].x * X_SCALE, xv[2 * mi + 1][1].y * X_SCALE);
                }
                // B fragments from resident smem + MMAs (warp-uniform guards)
#pragma unroll
                for (int ni = 0; ni < 8; ni++) {
                    if (nbase + ni * 8 < pact) {
                        const __half* wp = ws + (nbase + ni * 8 + l4) * WSTR + k0 + 2 * lm;
                        uint32_t b[2];
                        b[0] = *reinterpret_cast<const uint32_t*>(wp);
                        b[1] = *reinterpret_cast<const uint32_t*>(wp + 8);
                        mma16816(c[0][ni], a[0], b);
                        mma16816(c[1][ni], a[1], b);
                    }
                }
            }
        }

        // ---- row norms: reduce across the 4 lm lanes (lane = 4*l4 + lm) ----
        float xnr4[4];
#pragma unroll
        for (int r4 = 0; r4 < 4; r4++) {
            float s = xn4[r4];
            s += __shfl_xor_sync(0xffffffffu, s, 1);
            s += __shfl_xor_sync(0xffffffffu, s, 2);
            xnr4[r4] = X_SCALE * sqrtf(s);
        }

        // ---- epilogue: certified margin test + worklist ----
        float acc[2][2] = {{0.f, 0.f}, {0.f, 0.f}};
#pragma unroll
        for (int mi = 0; mi < 2; mi++)
#pragma unroll
            for (int ni = 0; ni < 8; ni++) {
                if (nbase + ni * 8 >= pact) continue;
#pragma unroll
                for (int cb = 0; cb < 2; cb++) {
                    int e = nbase + ni * 8 + 2 * lm + cb;
                    float ta = sta[e];
                    if (ta == 0.f) continue;
                    float tauw = ERR_COEF * swn[e];
#pragma unroll
                    for (int j = 0; j < 2; j++) {
                        float margin = c[mi][ni][2 * j + cb] + sbias[e];
                        float tau = tauw * xnr4[2 * mi + j];
                        if (margin > tau) {
                            acc[mi][j] += ta;
                        } else if (margin >= -tau) {
                            int row = mbase + mi * 16 + l4 + 8 * j;
                            int pos = atomicAdd(pcnt, 1);
                            if (pos < WLCAP) {
                                wl[pos] = (row << 8) | e;
                            } else {
                                const float* xp = x + (size_t)(rowBase + row) * FDIM;
                                const float* wp = Wg + (size_t)seid[e] * FDIM;
                                float s = 0.f;
                                for (int kk = 0; kk < FDIM; kk++) s += xp[kk] * wp[kk];
                                if (s + sbo[e] > 0.f) atomicAdd(&votes[row], ta);
                            }
                        }
                    }
                }
            }
#pragma unroll
        for (int mi = 0; mi < 2; mi++) {
            if (acc[mi][0] != 0.f) atomicAdd(&votes[mbase + mi * 16 + l4], acc[mi][0]);
            if (acc[mi][1] != 0.f) atomicAdd(&votes[mbase + mi * 16 + l4 + 8], acc[mi][1]);
        }
        __syncthreads();

        // ---- fixup: exact fp32 dot per worklist entry (1 warp / entry) ----
        int total = *pcnt;
        if (total > WLCAP) total = WLCAP;
        for (int idx = w; idx < total; idx += 8) {
            int ent = wl[idx];
            int row = ent >> 8, e = ent & 255;
            int er = seid[e];
            const float4* xp = reinterpret_cast<const float4*>(x + (size_t)(rowBase + row) * FDIM);
            const float4* wp = reinterpret_cast<const float4*>(Wg + (size_t)er * FDIM);
            float s = 0.f;
#pragma unroll
            for (int jj = 0; jj < 4; jj++) {
                float4 xv = xp[lane + jj * 32];
                float4 wv = wp[lane + jj * 32];
                s += xv.x * wv.x + xv.y * wv.y + xv.z * wv.z + xv.w * wv.w;
            }
#pragma unroll
            for (int o = 16; o; o >>= 1) s += __shfl_xor_sync(0xffffffffu, s, o);
            if (lane == 0) {
                if (s + sbo[e] > 0.f) atomicAdd(&votes[row], sta[e]);
            }
        }
        __syncthreads();
    }

    if (tid < 128) {
        int r = rowBase + tid;
        if (r < N) {
            float v = votes[tid];
            out[r] = (v > 0.f) ? 1.f : ((v < 0.f) ? -1.f : 0.f);
        }
    }
}

// ============================================================
// Launch
// ============================================================
extern "C" void kernel_launch(void* const* d_in, const int* in_sizes, int n_in,
                              void* d_out, int out_size) {
    const float* x      = (const float*)d_in[0];
    const float* W      = (const float*)d_in[1];
    const float* b      = (const float*)d_in[2];
    const float* alphas = (const float*)d_in[3];
    float* out = (float*)d_out;

    int E = in_sizes[2];   // 256
    int N = out_size;      // 131072

    cudaFuncSetAttribute(main_kernel, cudaFuncAttributeMaxDynamicSharedMemorySize,
                         SMEM_BYTES);

    pack_kernel<<<EMAX, 256>>>(W, b, alphas, E);
    int grid = (N + 127) / 128;
    main_kernel<<<grid, 256, SMEM_BYTES>>>(x, W, out, N);
}

// round 8
// speedup vs baseline: 1.8088x; 1.8088x over previous
#include <cuda_runtime.h>
#include <cuda_fp16.h>
#include <cstdint>

// ================= problem constants =================
#define FDIM 512
#define EMAX 256
#define X_SCALE 256.0f
#define W_SCALE 4096.0f
#define B_SCALE (X_SCALE * W_SCALE)

// ================= device scratch ====================
__device__ int    g_nactive;
__device__ int    g_npass;
__device__ float  g_ta[EMAX];
__device__ float  g_bias_s[EMAX];
__device__ __half g_Wh[EMAX * FDIM];
__device__ __half g_Wl[EMAX * FDIM];

// ================= PTX helpers =======================
__device__ __forceinline__ uint32_t smem_u32(const void* p) {
    uint32_t a;
    asm("{ .reg .u64 t; cvta.to.shared.u64 t, %1; cvt.u32.u64 %0, t; }" : "=r"(a) : "l"(p));
    return a;
}
__device__ __forceinline__ void cpa16(uint32_t dst, const void* src) {
    asm volatile("cp.async.cg.shared.global [%0], [%1], 16;" :: "r"(dst), "l"(src) : "memory");
}
__device__ __forceinline__ void cpa_commit() {
    asm volatile("cp.async.commit_group;" ::: "memory");
}
template <int NN> __device__ __forceinline__ void cpa_wait() {
    asm volatile("cp.async.wait_group %0;" :: "n"(NN) : "memory");
}
__device__ __forceinline__ void ldm4(uint32_t& r0, uint32_t& r1, uint32_t& r2, uint32_t& r3,
                                     uint32_t addr) {
    asm volatile("ldmatrix.sync.aligned.m8n8.x4.shared.b16 {%0,%1,%2,%3}, [%4];"
                 : "=r"(r0), "=r"(r1), "=r"(r2), "=r"(r3) : "r"(addr));
}
__device__ __forceinline__ void mma16816(float* c, const uint32_t* a, const uint32_t* b) {
    asm volatile(
        "mma.sync.aligned.m16n8k16.row.col.f32.f16.f16.f32 "
        "{%0,%1,%2,%3}, {%4,%5,%6,%7}, {%8,%9}, {%0,%1,%2,%3};"
        : "+f"(c[0]), "+f"(c[1]), "+f"(c[2]), "+f"(c[3])
        : "r"(a[0]), "r"(a[1]), "r"(a[2]), "r"(a[3]), "r"(b[0]), "r"(b[1]));
}

// ============================================================
// Prep: compaction + scaled fp16 hi/lo W packing. grid=EMAX x 256.
// ============================================================
__global__ __launch_bounds__(256) void pack_kernel(const float* __restrict__ W,
                                                   const float* __restrict__ bias,
                                                   const float* __restrict__ alphas,
                                                   int E) {
    __shared__ int   s_eidx[EMAX];
    __shared__ float s_ta[EMAX];
    __shared__ float s_b[EMAX];
    __shared__ int   wtot[8], woff[8];
    __shared__ int   s_na;

    int e = threadIdx.x;
    float ta = 0.f, bi = 0.f;
    int flag = 0;
    if (e < E) {
        ta = truncf(alphas[e]);
        bi = bias[e];
        flag = (ta != 0.f) ? 1 : 0;
    }
    unsigned mask = __ballot_sync(0xffffffffu, flag);
    int lane = e & 31, warp = e >> 5;
    int prefix = __popc(mask & ((1u << lane) - 1u));
    if (lane == 0) wtot[warp] = __popc(mask);
    s_eidx[e] = 0; s_ta[e] = 0.f; s_b[e] = 0.f;
    __syncthreads();
    if (e == 0) {
        int s = 0;
        for (int i = 0; i < 8; i++) { woff[i] = s; s += wtot[i]; }
        s_na = s;
    }
    __syncthreads();
    if (flag) {
        int pos = woff[warp] + prefix;
        s_eidx[pos] = e;
        s_ta[pos] = ta;
        s_b[pos] = bi;
    }
    __syncthreads();

    int na = s_na;
    if (blockIdx.x == 0) {
        g_ta[e]     = s_ta[e];
        g_bias_s[e] = s_b[e] * B_SCALE;
        if (e == 0) {
            g_nactive = na;
            int np = (na + 127) / 128;
            if (np < 1) np = 1;
            g_npass = np;
        }
    }

    int p = blockIdx.x, t = threadIdx.x;
    if (p < na) {
        int src = s_eidx[p];
        float2 v = *reinterpret_cast<const float2*>(W + (size_t)src * FDIM + 2 * t);
        float s0 = v.x * W_SCALE, s1 = v.y * W_SCALE;
        __half h0 = __float2half_rn(s0);
        __half h1 = __float2half_rn(s1);
        __half l0 = __float2half_rn(s0 - __half2float(h0));
        __half l1 = __float2half_rn(s1 - __half2float(h1));
        *reinterpret_cast<__half2*>(g_Wh + (size_t)p * FDIM + 2 * t) = __halves2half2(h0, h1);
        *reinterpret_cast<__half2*>(g_Wl + (size_t)p * FDIM + 2 * t) = __halves2half2(l0, l1);
    } else {
        __half2 z = __floats2half2_rn(0.f, 0.f);
        *reinterpret_cast<__half2*>(g_Wh + (size_t)p * FDIM + 2 * t) = z;
        *reinterpret_cast<__half2*>(g_Wl + (size_t)p * FDIM + 2 * t) = z;
    }
}

// ============================================================
// Main: R4 workload (3-term fp16 split, exact within fp32-class error),
// pipelined: cp.async W (hi+lo), register-staged x LDG before MMA phase,
// ldmatrix fragment loads, warp-uniform dead-tile skipping.
// 8 warps = 4(M) x 2(N); warp tile m32 x n64; 128 rows/CTA; KC=64.
// ============================================================
#define STR 72
#define TILE_B 18432                   // 128 * 72 * 2
#define OFF_XH0   0
#define OFF_XL0   (1 * TILE_B)
#define OFF_WH0   (2 * TILE_B)
#define OFF_WL0   (3 * TILE_B)
#define OFF_XH1   (4 * TILE_B)
#define OFF_XL1   (5 * TILE_B)
#define OFF_WH1   (6 * TILE_B)
#define OFF_WL1   (7 * TILE_B)
#define OFF_VOTES (8 * TILE_B)
#define OFF_SBIAS (OFF_VOTES + 512)
#define OFF_STA   (OFF_SBIAS + 512)
#define SMEM_BYTES (OFF_STA + 512 + 32)

__global__ __launch_bounds__(256, 1) void main_kernel(const float* __restrict__ x,
                                                      float* __restrict__ out,
                                                      int N) {
    extern __shared__ char sm[];
    uint32_t sb = smem_u32(sm);
    float* votes = reinterpret_cast<float*>(sm + OFF_VOTES);
    float* sbias = reinterpret_cast<float*>(sm + OFF_SBIAS);
    float* sta   = reinterpret_cast<float*>(sm + OFF_STA);

    const int tid = threadIdx.x, lane = tid & 31, w = tid >> 5;
    const int l4 = lane >> 2, lm = lane & 3, grp = lane >> 3, l8 = lane & 7;
    const int mwarp = w & 3, nwarp = w >> 2;
    const int mbase = mwarp * 32, nbase = nwarp * 64;
    const int rowBase = blockIdx.x * 128;
    const int c4 = tid & 15, rg = tid >> 4;

    if (tid < 128) votes[tid] = 0.f;
    const int na = g_nactive, npass = g_npass;

    const uint32_t xhB[2] = { sb + OFF_XH0, sb + OFF_XH1 };
    const uint32_t xlB[2] = { sb + OFF_XL0, sb + OFF_XL1 };
    const uint32_t whB[2] = { sb + OFF_WH0, sb + OFF_WH1 };
    const uint32_t wlB[2] = { sb + OFF_WL0, sb + OFF_WL1 };

    for (int pass = 0; pass < npass; pass++) {
        if (tid < 128) {
            int e = pass * 128 + tid;
            sbias[tid] = g_bias_s[e];
            sta[tid]   = g_ta[e];
        }
        int pact = na - pass * 128;
        if (pact > 128) pact = 128;
        if (pact < 0) pact = 0;

        float c[2][8][4];
#pragma unroll
        for (int mi = 0; mi < 2; mi++)
#pragma unroll
            for (int ni = 0; ni < 8; ni++)
#pragma unroll
                for (int j = 0; j < 4; j++) c[mi][ni][j] = 0.f;

        float4 xs[8];
        // ---- prologue: chunk 0 (x regs + W cp.async, then convert/store) ----
        {
            const float* xp = x + (size_t)rowBase * FDIM + c4 * 4;
#pragma unroll
            for (int i = 0; i < 8; i++)
                xs[i] = *reinterpret_cast<const float4*>(xp + (size_t)(i * 16 + rg) * FDIM);
#pragma unroll
            for (int jj = 0; jj < 2; jj++) {
                int unit = tid + jj * 256;            // 0..511 of 1024 per tile
                int u8 = unit & 7, r = unit >> 3;     // covers rows 0..63
                size_t go = (size_t)(pass * 128 + r) * FDIM + u8 * 8;
                cpa16(whB[0] + (uint32_t)(r * STR + u8 * 8) * 2, g_Wh + go);
                cpa16(wlB[0] + (uint32_t)(r * STR + u8 * 8) * 2, g_Wl + go);
                size_t go2 = (size_t)(pass * 128 + r + 64) * FDIM + u8 * 8;
                cpa16(whB[0] + (uint32_t)((r + 64) * STR + u8 * 8) * 2, g_Wh + go2);
                cpa16(wlB[0] + (uint32_t)((r + 64) * STR + u8 * 8) * 2, g_Wl + go2);
            }
            cpa_commit();
#pragma unroll
            for (int i = 0; i < 8; i++) {
                int row = i * 16 + rg;
                float s0 = xs[i].x * X_SCALE, s1 = xs[i].y * X_SCALE;
                float s2 = xs[i].z * X_SCALE, s3 = xs[i].w * X_SCALE;
                __half2 h01 = __floats2half2_rn(s0, s1);
                __half2 h23 = __floats2half2_rn(s2, s3);
                __half2 l01 = __floats2half2_rn(s0 - __low2float(h01), s1 - __high2float(h01));
                __half2 l23 = __floats2half2_rn(s2 - __low2float(h23), s3 - __high2float(h23));
                uint32_t ah = xhB[0] + (uint32_t)(row * STR + c4 * 4) * 2;
                uint32_t al = xlB[0] + (uint32_t)(row * STR + c4 * 4) * 2;
                asm volatile("st.shared.v2.b32 [%0], {%1,%2};"
                             :: "r"(ah), "r"(*reinterpret_cast<uint32_t*>(&h01)),
                                "r"(*reinterpret_cast<uint32_t*>(&h23)) : "memory");
                asm volatile("st.shared.v2.b32 [%0], {%1,%2};"
                             :: "r"(al), "r"(*reinterpret_cast<uint32_t*>(&l01)),
                                "r"(*reinterpret_cast<uint32_t*>(&l23)) : "memory");
            }
        }

        for (int kc = 0; kc < 8; kc++) {
            const int cur = kc & 1, nxt = cur ^ 1;
            if (kc < 7) {
                // stage next x chunk in regs + prefetch next W via cp.async
                const float* xp = x + (size_t)rowBase * FDIM + (kc + 1) * 64 + c4 * 4;
#pragma unroll
                for (int i = 0; i < 8; i++)
                    xs[i] = *reinterpret_cast<const float4*>(xp + (size_t)(i * 16 + rg) * FDIM);
#pragma unroll
                for (int jj = 0; jj < 2; jj++) {
                    int unit = tid + jj * 256;
                    int u8 = unit & 7, r = unit >> 3;
                    size_t go = (size_t)(pass * 128 + r) * FDIM + (kc + 1) * 64 + u8 * 8;
                    cpa16(whB[nxt] + (uint32_t)(r * STR + u8 * 8) * 2, g_Wh + go);
                    cpa16(wlB[nxt] + (uint32_t)(r * STR + u8 * 8) * 2, g_Wl + go);
                    size_t go2 = (size_t)(pass * 128 + r + 64) * FDIM + (kc + 1) * 64 + u8 * 8;
                    cpa16(whB[nxt] + (uint32_t)((r + 64) * STR + u8 * 8) * 2, g_Wh + go2);
                    cpa16(wlB[nxt] + (uint32_t)((r + 64) * STR + u8 * 8) * 2, g_Wl + go2);
                }
                cpa_commit();
                cpa_wait<1>();
            } else {
                cpa_wait<0>();
            }
            __syncthreads();

            // ---- MMA phase on current buffers (x LDG latency hides here) ----
#pragma unroll
            for (int ks = 0; ks < 4; ks++) {
                const int k0 = ks * 16;
                uint32_t ah[2][4], al[2][4];
#pragma unroll
                for (int mi = 0; mi < 2; mi++) {
                    int row = mbase + mi * 16 + (grp & 1) * 8 + l8;
                    int ko = k0 + (grp >> 1) * 8;
                    ldm4(ah[mi][0], ah[mi][1], ah[mi][2], ah[mi][3],
                         xhB[cur] + (uint32_t)(row * STR + ko) * 2);
                    ldm4(al[mi][0], al[mi][1], al[mi][2], al[mi][3],
                         xlB[cur] + (uint32_t)(row * STR + ko) * 2);
                }
                uint32_t bh[8][2], bl[8][2];
#pragma unroll
                for (int nn = 0; nn < 4; nn++) {
                    if (nbase + nn * 16 < pact) {
                        int nrow = nbase + nn * 16 + ((grp >> 1) & 1) * 8 + l8;
                        int ko = k0 + (grp & 1) * 8;
                        ldm4(bh[2 * nn][0], bh[2 * nn][1], bh[2 * nn + 1][0], bh[2 * nn + 1][1],
                             whB[cur] + (uint32_t)(nrow * STR + ko) * 2);
                        ldm4(bl[2 * nn][0], bl[2 * nn][1], bl[2 * nn + 1][0], bl[2 * nn + 1][1],
                             wlB[cur] + (uint32_t)(nrow * STR + ko) * 2);
                    }
                }
#pragma unroll
                for (int ni = 0; ni < 8; ni++) {
                    if (nbase + ni * 8 < pact) {
                        mma16816(c[0][ni], ah[0], bh[ni]);
                        mma16816(c[1][ni], ah[1], bh[ni]);
                        mma16816(c[0][ni], ah[0], bl[ni]);
                        mma16816(c[1][ni], ah[1], bl[ni]);
                        mma16816(c[0][ni], al[0], bh[ni]);
                        mma16816(c[1][ni], al[1], bh[ni]);
                    }
                }
            }

            // ---- convert + store next x chunk into the other buffers ----
            if (kc < 7) {
#pragma unroll
                for (int i = 0; i < 8; i++) {
                    int row = i * 16 + rg;
                    float s0 = xs[i].x * X_SCALE, s1 = xs[i].y * X_SCALE;
                    float s2 = xs[i].z * X_SCALE, s3 = xs[i].w * X_SCALE;
                    __half2 h01 = __floats2half2_rn(s0, s1);
                    __half2 h23 = __floats2half2_rn(s2, s3);
                    __half2 l01 = __floats2half2_rn(s0 - __low2float(h01), s1 - __high2float(h01));
                    __half2 l23 = __floats2half2_rn(s2 - __low2float(h23), s3 - __high2float(h23));
                    uint32_t ah2 = xhB[nxt] + (uint32_t)(row * STR + c4 * 4) * 2;
                    uint32_t al2 = xlB[nxt] + (uint32_t)(row * STR + c4 * 4) * 2;
                    asm volatile("st.shared.v2.b32 [%0], {%1,%2};"
                                 :: "r"(ah2), "r"(*reinterpret_cast<uint32_t*>(&h01)),
                                    "r"(*reinterpret_cast<uint32_t*>(&h23)) : "memory");
                    asm volatile("st.shared.v2.b32 [%0], {%1,%2};"
                                 :: "r"(al2), "r"(*reinterpret_cast<uint32_t*>(&l01)),
                                    "r"(*reinterpret_cast<uint32_t*>(&l23)) : "memory");
                }
            }
            __syncthreads();
        }

        // ---- epilogue: threshold + weighted vote (R4-proven) ----
        float acc[2][2] = {{0.f, 0.f}, {0.f, 0.f}};
#pragma unroll
        for (int mi = 0; mi < 2; mi++)
#pragma unroll
            for (int ni = 0; ni < 8; ni++) {
                if (nbase + ni * 8 >= pact) continue;
                int lc = nbase + ni * 8 + 2 * lm;
                float b0 = sbias[lc], b1 = sbias[lc + 1];
                float t0 = sta[lc],   t1 = sta[lc + 1];
                if (c[mi][ni][0] + b0 > 0.f) acc[mi][0] += t0;
                if (c[mi][ni][1] + b1 > 0.f) acc[mi][0] += t1;
                if (c[mi][ni][2] + b0 > 0.f) acc[mi][1] += t0;
                if (c[mi][ni][3] + b1 > 0.f) acc[mi][1] += t1;
            }
#pragma unroll
        for (int mi = 0; mi < 2; mi++) {
            if (acc[mi][0] != 0.f) atomicAdd(&votes[mbase + mi * 16 + l4], acc[mi][0]);
            if (acc[mi][1] != 0.f) atomicAdd(&votes[mbase + mi * 16 + l4 + 8], acc[mi][1]);
        }
        __syncthreads();
    }

    if (tid < 128) {
        int r = rowBase + tid;
        if (r < N) {
            float v = votes[tid];
            out[r] = (v > 0.f) ? 1.f : ((v < 0.f) ? -1.f : 0.f);
        }
    }
}

// ============================================================
// Launch
// ============================================================
extern "C" void kernel_launch(void* const* d_in, const int* in_sizes, int n_in,
                              void* d_out, int out_size) {
    const float* x      = (const float*)d_in[0];
    const float* W      = (const float*)d_in[1];
    const float* b      = (const float*)d_in[2];
    const float* alphas = (const float*)d_in[3];
    float* out = (float*)d_out;

    int E = in_sizes[2];   // 256
    int N = out_size;      // 131072

    cudaFuncSetAttribute(main_kernel, cudaFuncAttributeMaxDynamicSharedMemorySize,
                         SMEM_BYTES);

    pack_kernel<<<EMAX, 256>>>(W, b, alphas, E);
    int grid = (N + 127) / 128;
    main_kernel<<<grid, 256, SMEM_BYTES>>>(x, out, N);
}

// round 10
// speedup vs baseline: 1.8110x; 1.0012x over previous
#include <cuda_runtime.h>
#include <cuda_fp16.h>
#include <cstdint>

// ================= problem constants =================
#define FDIM 512
#define EMAX 256
#define X_SCALE 256.0f
#define W_SCALE 4096.0f
#define B_SCALE (X_SCALE * W_SCALE)

// ================= device scratch ====================
__device__ int    g_nactive;
__device__ int    g_npass;
__device__ float  g_ta[EMAX];
__device__ float  g_bias_s[EMAX];
__device__ __half g_Wh[EMAX * FDIM];
__device__ __half g_Wl[EMAX * FDIM];

// ================= PTX helpers =======================
__device__ __forceinline__ uint32_t smem_u32(const void* p) {
    uint32_t a;
    asm("{ .reg .u64 t; cvta.to.shared.u64 t, %1; cvt.u32.u64 %0, t; }" : "=r"(a) : "l"(p));
    return a;
}
__device__ __forceinline__ void cpa16(uint32_t dst, const void* src) {
    asm volatile("cp.async.cg.shared.global [%0], [%1], 16;" :: "r"(dst), "l"(src) : "memory");
}
__device__ __forceinline__ void cpa_commit() {
    asm volatile("cp.async.commit_group;" ::: "memory");
}
template <int NN> __device__ __forceinline__ void cpa_wait() {
    asm volatile("cp.async.wait_group %0;" :: "n"(NN) : "memory");
}
__device__ __forceinline__ void ldm4(uint32_t& r0, uint32_t& r1, uint32_t& r2, uint32_t& r3,
                                     uint32_t addr) {
    asm volatile("ldmatrix.sync.aligned.m8n8.x4.shared.b16 {%0,%1,%2,%3}, [%4];"
                 : "=r"(r0), "=r"(r1), "=r"(r2), "=r"(r3) : "r"(addr));
}
__device__ __forceinline__ void mma16816(float* c, const uint32_t* a, const uint32_t* b) {
    asm volatile(
        "mma.sync.aligned.m16n8k16.row.col.f32.f16.f16.f32 "
        "{%0,%1,%2,%3}, {%4,%5,%6,%7}, {%8,%9}, {%0,%1,%2,%3};"
        : "+f"(c[0]), "+f"(c[1]), "+f"(c[2]), "+f"(c[3])
        : "r"(a[0]), "r"(a[1]), "r"(a[2]), "r"(a[3]), "r"(b[0]), "r"(b[1]));
}

// ============================================================
// Prep: compaction + scaled fp16 hi/lo W packing. grid=EMAX x 256.
// (unchanged, validated)
// ============================================================
__global__ __launch_bounds__(256) void pack_kernel(const float* __restrict__ W,
                                                   const float* __restrict__ bias,
                                                   const float* __restrict__ alphas,
                                                   int E) {
    __shared__ int   s_eidx[EMAX];
    __shared__ float s_ta[EMAX];
    __shared__ float s_b[EMAX];
    __shared__ int   wtot[8], woff[8];
    __shared__ int   s_na;

    int e = threadIdx.x;
    float ta = 0.f, bi = 0.f;
    int flag = 0;
    if (e < E) {
        ta = truncf(alphas[e]);
        bi = bias[e];
        flag = (ta != 0.f) ? 1 : 0;
    }
    unsigned mask = __ballot_sync(0xffffffffu, flag);
    int lane = e & 31, warp = e >> 5;
    int prefix = __popc(mask & ((1u << lane) - 1u));
    if (lane == 0) wtot[warp] = __popc(mask);
    s_eidx[e] = 0; s_ta[e] = 0.f; s_b[e] = 0.f;
    __syncthreads();
    if (e == 0) {
        int s = 0;
        for (int i = 0; i < 8; i++) { woff[i] = s; s += wtot[i]; }
        s_na = s;
    }
    __syncthreads();
    if (flag) {
        int pos = woff[warp] + prefix;
        s_eidx[pos] = e;
        s_ta[pos] = ta;
        s_b[pos] = bi;
    }
    __syncthreads();

    int na = s_na;
    if (blockIdx.x == 0) {
        g_ta[e]     = s_ta[e];
        g_bias_s[e] = s_b[e] * B_SCALE;
        if (e == 0) {
            g_nactive = na;
            int np = (na + 127) / 128;
            if (np < 1) np = 1;
            g_npass = np;
        }
    }

    int p = blockIdx.x, t = threadIdx.x;
    if (p < na) {
        int src = s_eidx[p];
        float2 v = *reinterpret_cast<const float2*>(W + (size_t)src * FDIM + 2 * t);
        float s0 = v.x * W_SCALE, s1 = v.y * W_SCALE;
        __half h0 = __float2half_rn(s0);
        __half h1 = __float2half_rn(s1);
        __half l0 = __float2half_rn(s0 - __half2float(h0));
        __half l1 = __float2half_rn(s1 - __half2float(h1));
        *reinterpret_cast<__half2*>(g_Wh + (size_t)p * FDIM + 2 * t) = __halves2half2(h0, h1);
        *reinterpret_cast<__half2*>(g_Wl + (size_t)p * FDIM + 2 * t) = __halves2half2(l0, l1);
    } else {
        __half2 z = __floats2half2_rn(0.f, 0.f);
        *reinterpret_cast<__half2*>(g_Wh + (size_t)p * FDIM + 2 * t) = z;
        *reinterpret_cast<__half2*>(g_Wl + (size_t)p * FDIM + 2 * t) = z;
    }
}

// ============================================================
// Main: 64 rows/CTA (2 CTAs/SM), 3-term fp16 split, pipelined.
// 8 warps = 2(M) x 4(N); warp tile m32 x n32; KC=64.
// ============================================================
#define STR 72
#define XTILE_B 9216                   // 64 * 72 * 2
#define WTILE_B 18432                  // 128 * 72 * 2
#define OFF_XH0   0
#define OFF_XL0   (OFF_XH0 + XTILE_B)
#define OFF_XH1   (OFF_XL0 + XTILE_B)
#define OFF_XL1   (OFF_XH1 + XTILE_B)
#define OFF_WH0   (OFF_XL1 + XTILE_B)
#define OFF_WL0   (OFF_WH0 + WTILE_B)
#define OFF_WH1   (OFF_WL0 + WTILE_B)
#define OFF_WL1   (OFF_WH1 + WTILE_B)
#define OFF_VOTES (OFF_WL1 + WTILE_B)
#define OFF_SBIAS (OFF_VOTES + 256)
#define OFF_STA   (OFF_SBIAS + 512)
#define SMEM_BYTES (OFF_STA + 512 + 32)

__global__ __launch_bounds__(256, 2) void main_kernel(const float* __restrict__ x,
                                                      float* __restrict__ out,
                                                      int N) {
    extern __shared__ char sm[];
    uint32_t sb = smem_u32(sm);
    float* votes = reinterpret_cast<float*>(sm + OFF_VOTES);
    float* sbias = reinterpret_cast<float*>(sm + OFF_SBIAS);
    float* sta   = reinterpret_cast<float*>(sm + OFF_STA);

    const int tid = threadIdx.x, lane = tid & 31, w = tid >> 5;
    const int l4 = lane >> 2, lm = lane & 3, grp = lane >> 3, l8 = lane & 7;
    const int mwarp = w & 1, nwarp = w >> 1;
    const int mbase = mwarp * 32, nbase = nwarp * 32;
    const int rowBase = blockIdx.x * 64;
    const int c4 = tid & 15, rg = tid >> 4;

    if (tid < 64) votes[tid] = 0.f;
    const int na = g_nactive, npass = g_npass;

    const uint32_t xhB[2] = { sb + OFF_XH0, sb + OFF_XH1 };
    const uint32_t xlB[2] = { sb + OFF_XL0, sb + OFF_XL1 };
    const uint32_t whB[2] = { sb + OFF_WH0, sb + OFF_WH1 };
    const uint32_t wlB[2] = { sb + OFF_WL0, sb + OFF_WL1 };

    for (int pass = 0; pass < npass; pass++) {
        if (tid < 128) {
            int e = pass * 128 + tid;
            sbias[tid] = g_bias_s[e];
            sta[tid]   = g_ta[e];
        }
        int pact = na - pass * 128;
        if (pact > 128) pact = 128;
        if (pact < 0) pact = 0;

        float c[2][4][4];
#pragma unroll
        for (int mi = 0; mi < 2; mi++)
#pragma unroll
            for (int ni = 0; ni < 4; ni++)
#pragma unroll
                for (int j = 0; j < 4; j++) c[mi][ni][j] = 0.f;

        float4 xs[4];
        // ---- prologue: chunk 0 ----
        {
            const float* xp = x + (size_t)rowBase * FDIM + c4 * 4;
#pragma unroll
            for (int i = 0; i < 4; i++)
                xs[i] = *reinterpret_cast<const float4*>(xp + (size_t)(i * 16 + rg) * FDIM);
#pragma unroll
            for (int jj = 0; jj < 4; jj++) {
                int unit = tid + jj * 256;            // 0..1023
                int u8 = unit & 7, r = unit >> 3;     // rows 0..127
                size_t go = (size_t)(pass * 128 + r) * FDIM + u8 * 8;
                cpa16(whB[0] + (uint32_t)(r * STR + u8 * 8) * 2, g_Wh + go);
                cpa16(wlB[0] + (uint32_t)(r * STR + u8 * 8) * 2, g_Wl + go);
            }
            cpa_commit();
#pragma unroll
            for (int i = 0; i < 4; i++) {
                int row = i * 16 + rg;
                float s0 = xs[i].x * X_SCALE, s1 = xs[i].y * X_SCALE;
                float s2 = xs[i].z * X_SCALE, s3 = xs[i].w * X_SCALE;
                __half2 h01 = __floats2half2_rn(s0, s1);
                __half2 h23 = __floats2half2_rn(s2, s3);
                __half2 l01 = __floats2half2_rn(s0 - __low2float(h01), s1 - __high2float(h01));
                __half2 l23 = __floats2half2_rn(s2 - __low2float(h23), s3 - __high2float(h23));
                uint32_t ah = xhB[0] + (uint32_t)(row * STR + c4 * 4) * 2;
                uint32_t al = xlB[0] + (uint32_t)(row * STR + c4 * 4) * 2;
                asm volatile("st.shared.v2.b32 [%0], {%1,%2};"
                             :: "r"(ah), "r"(*reinterpret_cast<uint32_t*>(&h01)),
                                "r"(*reinterpret_cast<uint32_t*>(&h23)) : "memory");
                asm volatile("st.shared.v2.b32 [%0], {%1,%2};"
                             :: "r"(al), "r"(*reinterpret_cast<uint32_t*>(&l01)),
                                "r"(*reinterpret_cast<uint32_t*>(&l23)) : "memory");
            }
        }

        for (int kc = 0; kc < 8; kc++) {
            const int cur = kc & 1, nxt = cur ^ 1;
            if (kc < 7) {
                const float* xp = x + (size_t)rowBase * FDIM + (kc + 1) * 64 + c4 * 4;
#pragma unroll
                for (int i = 0; i < 4; i++)
                    xs[i] = *reinterpret_cast<const float4*>(xp + (size_t)(i * 16 + rg) * FDIM);
#pragma unroll
                for (int jj = 0; jj < 4; jj++) {
                    int unit = tid + jj * 256;
                    int u8 = unit & 7, r = unit >> 3;
                    size_t go = (size_t)(pass * 128 + r) * FDIM + (kc + 1) * 64 + u8 * 8;
                    cpa16(whB[nxt] + (uint32_t)(r * STR + u8 * 8) * 2, g_Wh + go);
                    cpa16(wlB[nxt] + (uint32_t)(r * STR + u8 * 8) * 2, g_Wl + go);
                }
                cpa_commit();
                cpa_wait<1>();
            } else {
                cpa_wait<0>();
            }
            __syncthreads();

            // ---- MMA phase ----
#pragma unroll
            for (int ks = 0; ks < 4; ks++) {
                const int k0 = ks * 16;
                uint32_t ah[2][4], al[2][4];
#pragma unroll
                for (int mi = 0; mi < 2; mi++) {
                    int row = mbase + mi * 16 + (grp & 1) * 8 + l8;
                    int ko = k0 + (grp >> 1) * 8;
                    ldm4(ah[mi][0], ah[mi][1], ah[mi][2], ah[mi][3],
                         xhB[cur] + (uint32_t)(row * STR + ko) * 2);
                    ldm4(al[mi][0], al[mi][1], al[mi][2], al[mi][3],
                         xlB[cur] + (uint32_t)(row * STR + ko) * 2);
                }
                uint32_t bh[4][2], bl[4][2];
#pragma unroll
                for (int nn = 0; nn < 2; nn++) {
                    if (nbase + nn * 16 < pact) {
                        int nrow = nbase + nn * 16 + ((grp >> 1) & 1) * 8 + l8;
                        int ko = k0 + (grp & 1) * 8;
                        ldm4(bh[2 * nn][0], bh[2 * nn][1], bh[2 * nn + 1][0], bh[2 * nn + 1][1],
                             whB[cur] + (uint32_t)(nrow * STR + ko) * 2);
                        ldm4(bl[2 * nn][0], bl[2 * nn][1], bl[2 * nn + 1][0], bl[2 * nn + 1][1],
                             wlB[cur] + (uint32_t)(nrow * STR + ko) * 2);
                    }
                }
#pragma unroll
                for (int ni = 0; ni < 4; ni++) {
                    if (nbase + ni * 8 < pact) {
                        mma16816(c[0][ni], ah[0], bh[ni]);
                        mma16816(c[1][ni], ah[1], bh[ni]);
                        mma16816(c[0][ni], ah[0], bl[ni]);
                        mma16816(c[1][ni], ah[1], bl[ni]);
                        mma16816(c[0][ni], al[0], bh[ni]);
                        mma16816(c[1][ni], al[1], bh[ni]);
                    }
                }
            }

            // ---- convert + store next x chunk ----
            if (kc < 7) {
#pragma unroll
                for (int i = 0; i < 4; i++) {
                    int row = i * 16 + rg;
                    float s0 = xs[i].x * X_SCALE, s1 = xs[i].y * X_SCALE;
                    float s2 = xs[i].z * X_SCALE, s3 = xs[i].w * X_SCALE;
                    __half2 h01 = __floats2half2_rn(s0, s1);
                    __half2 h23 = __floats2half2_rn(s2, s3);
                    __half2 l01 = __floats2half2_rn(s0 - __low2float(h01), s1 - __high2float(h01));
                    __half2 l23 = __floats2half2_rn(s2 - __low2float(h23), s3 - __high2float(h23));
                    uint32_t ah2 = xhB[nxt] + (uint32_t)(row * STR + c4 * 4) * 2;
                    uint32_t al2 = xlB[nxt] + (uint32_t)(row * STR + c4 * 4) * 2;
                    asm volatile("st.shared.v2.b32 [%0], {%1,%2};"
                                 :: "r"(ah2), "r"(*reinterpret_cast<uint32_t*>(&h01)),
                                    "r"(*reinterpret_cast<uint32_t*>(&h23)) : "memory");
                    asm volatile("st.shared.v2.b32 [%0], {%1,%2};"
                                 :: "r"(al2), "r"(*reinterpret_cast<uint32_t*>(&l01)),
                                    "r"(*reinterpret_cast<uint32_t*>(&l23)) : "memory");
                }
            }
            __syncthreads();
        }

        // ---- epilogue: threshold + weighted vote ----
        float acc[2][2] = {{0.f, 0.f}, {0.f, 0.f}};
#pragma unroll
        for (int mi = 0; mi < 2; mi++)
#pragma unroll
            for (int ni = 0; ni < 4; ni++) {
                if (nbase + ni * 8 >= pact) continue;
                int lc = nbase + ni * 8 + 2 * lm;
                float b0 = sbias[lc], b1 = sbias[lc + 1];
                float t0 = sta[lc],   t1 = sta[lc + 1];
                if (c[mi][ni][0] + b0 > 0.f) acc[mi][0] += t0;
                if (c[mi][ni][1] + b1 > 0.f) acc[mi][0] += t1;
                if (c[mi][ni][2] + b0 > 0.f) acc[mi][1] += t0;
                if (c[mi][ni][3] + b1 > 0.f) acc[mi][1] += t1;
            }
#pragma unroll
        for (int mi = 0; mi < 2; mi++) {
            if (acc[mi][0] != 0.f) atomicAdd(&votes[mbase + mi * 16 + l4], acc[mi][0]);
            if (acc[mi][1] != 0.f) atomicAdd(&votes[mbase + mi * 16 + l4 + 8], acc[mi][1]);
        }
        __syncthreads();
    }

    if (tid < 64) {
        int r = rowBase + tid;
        if (r < N) {
            float v = votes[tid];
            out[r] = (v > 0.f) ? 1.f : ((v < 0.f) ? -1.f : 0.f);
        }
    }
}

// ============================================================
// Launch
// ============================================================
extern "C" void kernel_launch(void* const* d_in, const int* in_sizes, int n_in,
                              void* d_out, int out_size) {
    const float* x      = (const float*)d_in[0];
    const float* W      = (const float*)d_in[1];
    const float* b      = (const float*)d_in[2];
    const float* alphas = (const float*)d_in[3];
    float* out = (float*)d_out;

    int E = in_sizes[2];   // 256
    int N = out_size;      // 131072

    cudaFuncSetAttribute(main_kernel, cudaFuncAttributeMaxDynamicSharedMemorySize,
                         SMEM_BYTES);

    pack_kernel<<<EMAX, 256>>>(W, b, alphas, E);
    int grid = (N + 63) / 64;
    main_kernel<<<grid, 256, SMEM_BYTES>>>(x, out, N);
}

// round 11
// speedup vs baseline: 1.8718x; 1.0336x over previous
#include <cuda_runtime.h>
#include <cuda_fp16.h>
#include <cstdint>

// ================= problem constants =================
#define FDIM 512
#define EMAX 256
#define X_SCALE 256.0f
#define W_SCALE 4096.0f
#define B_SCALE (X_SCALE * W_SCALE)

// ================= device scratch ====================
__device__ int    g_nactive;
__device__ int    g_npass;
__device__ float  g_ta[EMAX];
__device__ float  g_bias_s[EMAX];
__device__ __half g_Wh[EMAX * FDIM];
__device__ __half g_Wl[EMAX * FDIM];

// ================= PTX helpers =======================
__device__ __forceinline__ uint32_t smem_u32(const void* p) {
    uint32_t a;
    asm("{ .reg .u64 t; cvta.to.shared.u64 t, %1; cvt.u32.u64 %0, t; }" : "=r"(a) : "l"(p));
    return a;
}
__device__ __forceinline__ void cpa16(uint32_t dst, const void* src) {
    asm volatile("cp.async.cg.shared.global [%0], [%1], 16;" :: "r"(dst), "l"(src) : "memory");
}
__device__ __forceinline__ void cpa_commit() {
    asm volatile("cp.async.commit_group;" ::: "memory");
}
template <int NN> __device__ __forceinline__ void cpa_wait() {
    asm volatile("cp.async.wait_group %0;" :: "n"(NN) : "memory");
}
__device__ __forceinline__ void ldm4(uint32_t& r0, uint32_t& r1, uint32_t& r2, uint32_t& r3,
                                     uint32_t addr) {
    asm volatile("ldmatrix.sync.aligned.m8n8.x4.shared.b16 {%0,%1,%2,%3}, [%4];"
                 : "=r"(r0), "=r"(r1), "=r"(r2), "=r"(r3) : "r"(addr));
}
__device__ __forceinline__ void ldm2(uint32_t& r0, uint32_t& r1, uint32_t addr) {
    asm volatile("ldmatrix.sync.aligned.m8n8.x2.shared.b16 {%0,%1}, [%2];"
                 : "=r"(r0), "=r"(r1) : "r"(addr));
}
__device__ __forceinline__ void mma16816(float* c, const uint32_t* a, const uint32_t* b) {
    asm volatile(
        "mma.sync.aligned.m16n8k16.row.col.f32.f16.f16.f32 "
        "{%0,%1,%2,%3}, {%4,%5,%6,%7}, {%8,%9}, {%0,%1,%2,%3};"
        : "+f"(c[0]), "+f"(c[1]), "+f"(c[2]), "+f"(c[3])
        : "r"(a[0]), "r"(a[1]), "r"(a[2]), "r"(a[3]), "r"(b[0]), "r"(b[1]));
}

// ============================================================
// Prep: compaction + scaled fp16 hi/lo W packing. grid=EMAX x 256.
// (unchanged, validated)
// ============================================================
__global__ __launch_bounds__(256) void pack_kernel(const float* __restrict__ W,
                                                   const float* __restrict__ bias,
                                                   const float* __restrict__ alphas,
                                                   int E) {
    __shared__ int   s_eidx[EMAX];
    __shared__ float s_ta[EMAX];
    __shared__ float s_b[EMAX];
    __shared__ int   wtot[8], woff[8];
    __shared__ int   s_na;

    int e = threadIdx.x;
    float ta = 0.f, bi = 0.f;
    int flag = 0;
    if (e < E) {
        ta = truncf(alphas[e]);
        bi = bias[e];
        flag = (ta != 0.f) ? 1 : 0;
    }
    unsigned mask = __ballot_sync(0xffffffffu, flag);
    int lane = e & 31, warp = e >> 5;
    int prefix = __popc(mask & ((1u << lane) - 1u));
    if (lane == 0) wtot[warp] = __popc(mask);
    s_eidx[e] = 0; s_ta[e] = 0.f; s_b[e] = 0.f;
    __syncthreads();
    if (e == 0) {
        int s = 0;
        for (int i = 0; i < 8; i++) { woff[i] = s; s += wtot[i]; }
        s_na = s;
    }
    __syncthreads();
    if (flag) {
        int pos = woff[warp] + prefix;
        s_eidx[pos] = e;
        s_ta[pos] = ta;
        s_b[pos] = bi;
    }
    __syncthreads();

    int na = s_na;
    if (blockIdx.x == 0) {
        g_ta[e]     = s_ta[e];
        g_bias_s[e] = s_b[e] * B_SCALE;
        if (e == 0) {
            g_nactive = na;
            int np = (na + 127) / 128;
            if (np < 1) np = 1;
            g_npass = np;
        }
    }

    int p = blockIdx.x, t = threadIdx.x;
    if (p < na) {
        int src = s_eidx[p];
        float2 v = *reinterpret_cast<const float2*>(W + (size_t)src * FDIM + 2 * t);
        float s0 = v.x * W_SCALE, s1 = v.y * W_SCALE;
        __half h0 = __float2half_rn(s0);
        __half h1 = __float2half_rn(s1);
        __half l0 = __float2half_rn(s0 - __half2float(h0));
        __half l1 = __float2half_rn(s1 - __half2float(h1));
        *reinterpret_cast<__half2*>(g_Wh + (size_t)p * FDIM + 2 * t) = __halves2half2(h0, h1);
        *reinterpret_cast<__half2*>(g_Wl + (size_t)p * FDIM + 2 * t) = __halves2half2(l0, l1);
    } else {
        __half2 z = __floats2half2_rn(0.f, 0.f);
        *reinterpret_cast<__half2*>(g_Wh + (size_t)p * FDIM + 2 * t) = z;
        *reinterpret_cast<__half2*>(g_Wl + (size_t)p * FDIM + 2 * t) = z;
    }
}

// ============================================================
// Main: 64 rows/CTA (2 CTAs/SM), 3-term fp16 split, pipelined.
// 8 warps = 2(M) x 4(N); STRIPED n-tiles: warp nwarp owns tiles
// {nwarp, nwarp+4, nwarp+8, nwarp+12}; term-major MMA ordering.
// ============================================================
#define STR 72
#define XTILE_B 9216                   // 64 * 72 * 2
#define WTILE_B 18432                  // 128 * 72 * 2
#define OFF_XH0   0
#define OFF_XL0   (OFF_XH0 + XTILE_B)
#define OFF_XH1   (OFF_XL0 + XTILE_B)
#define OFF_XL1   (OFF_XH1 + XTILE_B)
#define OFF_WH0   (OFF_XL1 + XTILE_B)
#define OFF_WL0   (OFF_WH0 + WTILE_B)
#define OFF_WH1   (OFF_WL0 + WTILE_B)
#define OFF_WL1   (OFF_WH1 + WTILE_B)
#define OFF_VOTES (OFF_WL1 + WTILE_B)
#define OFF_SBIAS (OFF_VOTES + 256)
#define OFF_STA   (OFF_SBIAS + 512)
#define SMEM_BYTES (OFF_STA + 512 + 32)

__global__ __launch_bounds__(256, 2) void main_kernel(const float* __restrict__ x,
                                                      float* __restrict__ out,
                                                      int N) {
    extern __shared__ char sm[];
    uint32_t sb = smem_u32(sm);
    float* votes = reinterpret_cast<float*>(sm + OFF_VOTES);
    float* sbias = reinterpret_cast<float*>(sm + OFF_SBIAS);
    float* sta   = reinterpret_cast<float*>(sm + OFF_STA);

    const int tid = threadIdx.x, lane = tid & 31, w = tid >> 5;
    const int l4 = lane >> 2, lm = lane & 3, grp = lane >> 3, l8 = lane & 7;
    const int mwarp = w & 1, nwarp = w >> 1;
    const int mbase = mwarp * 32;
    const int rowBase = blockIdx.x * 64;
    const int c4 = tid & 15, rg = tid >> 4;

    if (tid < 64) votes[tid] = 0.f;
    const int na = g_nactive, npass = g_npass;

    const uint32_t xhB[2] = { sb + OFF_XH0, sb + OFF_XH1 };
    const uint32_t xlB[2] = { sb + OFF_XL0, sb + OFF_XL1 };
    const uint32_t whB[2] = { sb + OFF_WH0, sb + OFF_WH1 };
    const uint32_t wlB[2] = { sb + OFF_WL0, sb + OFF_WL1 };

    for (int pass = 0; pass < npass; pass++) {
        if (tid < 128) {
            int e = pass * 128 + tid;
            sbias[tid] = g_bias_s[e];
            sta[tid]   = g_ta[e];
        }
        int pact = na - pass * 128;
        if (pact > 128) pact = 128;
        if (pact < 0) pact = 0;
        const int pactR = (pact + 7) & ~7;   // rows of W actually needed

        // striped tiles for this warp: tile(j) = nwarp + 4*j
        float c[2][4][4];
#pragma unroll
        for (int mi = 0; mi < 2; mi++)
#pragma unroll
            for (int j = 0; j < 4; j++)
#pragma unroll
                for (int q = 0; q < 4; q++) c[mi][j][q] = 0.f;

        float4 xs[4];
        // ---- prologue: chunk 0 ----
        {
            const float* xp = x + (size_t)rowBase * FDIM + c4 * 4;
#pragma unroll
            for (int i = 0; i < 4; i++)
                xs[i] = *reinterpret_cast<const float4*>(xp + (size_t)(i * 16 + rg) * FDIM);
#pragma unroll
            for (int jj = 0; jj < 4; jj++) {
                int unit = tid + jj * 256;            // 0..1023
                int u8 = unit & 7, r = unit >> 3;     // rows 0..127
                if (r < pactR) {
                    size_t go = (size_t)(pass * 128 + r) * FDIM + u8 * 8;
                    cpa16(whB[0] + (uint32_t)(r * STR + u8 * 8) * 2, g_Wh + go);
                    cpa16(wlB[0] + (uint32_t)(r * STR + u8 * 8) * 2, g_Wl + go);
                }
            }
            cpa_commit();
#pragma unroll
            for (int i = 0; i < 4; i++) {
                int row = i * 16 + rg;
                float s0 = xs[i].x * X_SCALE, s1 = xs[i].y * X_SCALE;
                float s2 = xs[i].z * X_SCALE, s3 = xs[i].w * X_SCALE;
                __half2 h01 = __floats2half2_rn(s0, s1);
                __half2 h23 = __floats2half2_rn(s2, s3);
                __half2 l01 = __floats2half2_rn(s0 - __low2float(h01), s1 - __high2float(h01));
                __half2 l23 = __floats2half2_rn(s2 - __low2float(h23), s3 - __high2float(h23));
                uint32_t ah = xhB[0] + (uint32_t)(row * STR + c4 * 4) * 2;
                uint32_t al = xlB[0] + (uint32_t)(row * STR + c4 * 4) * 2;
                asm volatile("st.shared.v2.b32 [%0], {%1,%2};"
                             :: "r"(ah), "r"(*reinterpret_cast<uint32_t*>(&h01)),
                                "r"(*reinterpret_cast<uint32_t*>(&h23)) : "memory");
                asm volatile("st.shared.v2.b32 [%0], {%1,%2};"
                             :: "r"(al), "r"(*reinterpret_cast<uint32_t*>(&l01)),
                                "r"(*reinterpret_cast<uint32_t*>(&l23)) : "memory");
            }
        }

        for (int kc = 0; kc < 8; kc++) {
            const int cur = kc & 1, nxt = cur ^ 1;
            if (kc < 7) {
                const float* xp = x + (size_t)rowBase * FDIM + (kc + 1) * 64 + c4 * 4;
#pragma unroll
                for (int i = 0; i < 4; i++)
                    xs[i] = *reinterpret_cast<const float4*>(xp + (size_t)(i * 16 + rg) * FDIM);
#pragma unroll
                for (int jj = 0; jj < 4; jj++) {
                    int unit = tid + jj * 256;
                    int u8 = unit & 7, r = unit >> 3;
                    if (r < pactR) {
                        size_t go = (size_t)(pass * 128 + r) * FDIM + (kc + 1) * 64 + u8 * 8;
                        cpa16(whB[nxt] + (uint32_t)(r * STR + u8 * 8) * 2, g_Wh + go);
                        cpa16(wlB[nxt] + (uint32_t)(r * STR + u8 * 8) * 2, g_Wl + go);
                    }
                }
                cpa_commit();
                cpa_wait<1>();
            } else {
                cpa_wait<0>();
            }
            __syncthreads();

            // ---- MMA phase: term-major ordering, striped tiles ----
#pragma unroll
            for (int ks = 0; ks < 4; ks++) {
                const int k0 = ks * 16;
                uint32_t ah[2][4], al[2][4];
#pragma unroll
                for (int mi = 0; mi < 2; mi++) {
                    int row = mbase + mi * 16 + (grp & 1) * 8 + l8;
                    int ko = k0 + (grp >> 1) * 8;
                    ldm4(ah[mi][0], ah[mi][1], ah[mi][2], ah[mi][3],
                         xhB[cur] + (uint32_t)(row * STR + ko) * 2);
                    ldm4(al[mi][0], al[mi][1], al[mi][2], al[mi][3],
                         xlB[cur] + (uint32_t)(row * STR + ko) * 2);
                }
                // B fragments: one x2 per live tile (hi and lo)
                uint32_t bh[4][2], bl[4][2];
#pragma unroll
                for (int j = 0; j < 4; j++) {
                    int tId = nwarp + 4 * j;
                    if (tId * 8 < pact) {
                        uint32_t off = (uint32_t)((tId * 8 + l8) * STR + k0 + (grp & 1) * 8) * 2;
                        ldm2(bh[j][0], bh[j][1], whB[cur] + off);
                        ldm2(bl[j][0], bl[j][1], wlB[cur] + off);
                    }
                }
                // term hh
#pragma unroll
                for (int j = 0; j < 4; j++) {
                    if ((nwarp + 4 * j) * 8 < pact) {
                        mma16816(c[0][j], ah[0], bh[j]);
                        mma16816(c[1][j], ah[1], bh[j]);
                    }
                }
                // term hl
#pragma unroll
                for (int j = 0; j < 4; j++) {
                    if ((nwarp + 4 * j) * 8 < pact) {
                        mma16816(c[0][j], ah[0], bl[j]);
                        mma16816(c[1][j], ah[1], bl[j]);
                    }
                }
                // term lh
#pragma unroll
                for (int j = 0; j < 4; j++) {
                    if ((nwarp + 4 * j) * 8 < pact) {
                        mma16816(c[0][j], al[0], bh[j]);
                        mma16816(c[1][j], al[1], bh[j]);
                    }
                }
            }

            // ---- convert + store next x chunk ----
            if (kc < 7) {
#pragma unroll
                for (int i = 0; i < 4; i++) {
                    int row = i * 16 + rg;
                    float s0 = xs[i].x * X_SCALE, s1 = xs[i].y * X_SCALE;
                    float s2 = xs[i].z * X_SCALE, s3 = xs[i].w * X_SCALE;
                    __half2 h01 = __floats2half2_rn(s0, s1);
                    __half2 h23 = __floats2half2_rn(s2, s3);
                    __half2 l01 = __floats2half2_rn(s0 - __low2float(h01), s1 - __high2float(h01));
                    __half2 l23 = __floats2half2_rn(s2 - __low2float(h23), s3 - __high2float(h23));
                    uint32_t ah2 = xhB[nxt] + (uint32_t)(row * STR + c4 * 4) * 2;
                    uint32_t al2 = xlB[nxt] + (uint32_t)(row * STR + c4 * 4) * 2;
                    asm volatile("st.shared.v2.b32 [%0], {%1,%2};"
                                 :: "r"(ah2), "r"(*reinterpret_cast<uint32_t*>(&h01)),
                                    "r"(*reinterpret_cast<uint32_t*>(&h23)) : "memory");
                    asm volatile("st.shared.v2.b32 [%0], {%1,%2};"
                                 :: "r"(al2), "r"(*reinterpret_cast<uint32_t*>(&l01)),
                                    "r"(*reinterpret_cast<uint32_t*>(&l23)) : "memory");
                }
            }
            __syncthreads();
        }

        // ---- epilogue: threshold + weighted vote (striped tile map) ----
        float acc[2][2] = {{0.f, 0.f}, {0.f, 0.f}};
#pragma unroll
        for (int mi = 0; mi < 2; mi++)
#pragma unroll
            for (int j = 0; j < 4; j++) {
                int tId = nwarp + 4 * j;
                if (tId * 8 >= pact) continue;
                int lc = tId * 8 + 2 * lm;
                float b0 = sbias[lc], b1 = sbias[lc + 1];
                float t0 = sta[lc],   t1 = sta[lc + 1];
                if (c[mi][j][0] + b0 > 0.f) acc[mi][0] += t0;
                if (c[mi][j][1] + b1 > 0.f) acc[mi][0] += t1;
                if (c[mi][j][2] + b0 > 0.f) acc[mi][1] += t0;
                if (c[mi][j][3] + b1 > 0.f) acc[mi][1] += t1;
            }
#pragma unroll
        for (int mi = 0; mi < 2; mi++) {
            if (acc[mi][0] != 0.f) atomicAdd(&votes[mbase + mi * 16 + l4], acc[mi][0]);
            if (acc[mi][1] != 0.f) atomicAdd(&votes[mbase + mi * 16 + l4 + 8], acc[mi][1]);
        }
        __syncthreads();
    }

    if (tid < 64) {
        int r = rowBase + tid;
        if (r < N) {
            float v = votes[tid];
            out[r] = (v > 0.f) ? 1.f : ((v < 0.f) ? -1.f : 0.f);
        }
    }
}

// ============================================================
// Launch
// ============================================================
extern "C" void kernel_launch(void* const* d_in, const int* in_sizes, int n_in,
                              void* d_out, int out_size) {
    const float* x      = (const float*)d_in[0];
    const float* W      = (const float*)d_in[1];
    const float* b      = (const float*)d_in[2];
    const float* alphas = (const float*)d_in[3];
    float* out = (float*)d_out;

    int E = in_sizes[2];   // 256
    int N = out_size;      // 131072

    cudaFuncSetAttribute(main_kernel, cudaFuncAttributeMaxDynamicSharedMemorySize,
                         SMEM_BYTES);

    pack_kernel<<<EMAX, 256>>>(W, b, alphas, E);
    int grid = (N + 63) / 64;
    main_kernel<<<grid, 256, SMEM_BYTES>>>(x, out, N);
}

// round 14
// speedup vs baseline: 2.7800x; 1.4852x over previous
#include <cuda_runtime.h>
#include <cuda_fp16.h>
#include <cstdint>

// ================= problem constants =================
#define FDIM 512
#define EMAX 256
#define EPP  96                        // estimators per pass (12 n-tiles)
#define X_SCALE 256.0f
#define W_SCALE 4096.0f
#define B_SCALE (X_SCALE * W_SCALE)

// ================= device scratch ====================
__device__ int    g_nactive;
__device__ int    g_npass;
__device__ float  g_ta[EMAX];
__device__ float  g_bias_s[EMAX];
__device__ __half g_Wh[EMAX * FDIM];
__device__ __half g_Wl[EMAX * FDIM];

// ================= PTX helpers =======================
__device__ __forceinline__ uint32_t smem_u32(const void* p) {
    uint32_t a;
    asm("{ .reg .u64 t; cvta.to.shared.u64 t, %1; cvt.u32.u64 %0, t; }" : "=r"(a) : "l"(p));
    return a;
}
__device__ __forceinline__ void cpa16(uint32_t dst, const void* src) {
    asm volatile("cp.async.cg.shared.global [%0], [%1], 16;" :: "r"(dst), "l"(src) : "memory");
}
// .noinc: does NOT bump expected-arrival count; init count must include these
// 128 completions explicitly (fullM init = 128 STS-arrives + 128 noinc = 256).
__device__ __forceinline__ void cpa_mbar_arrive_noinc(uint32_t mbar) {
    asm volatile("cp.async.mbarrier.arrive.noinc.shared::cta.b64 [%0];" :: "r"(mbar) : "memory");
}
#define MBAR_INIT(addr, cnt) \
    asm volatile("mbarrier.init.shared.b64 [%0], %1;" :: "r"(addr), "r"(cnt) : "memory")
#define MBAR_ARRIVE(addr) \
    asm volatile("mbarrier.arrive.shared.b64 _, [%0];" :: "r"(addr) : "memory")
#define MBAR_WAIT(addr, parity) do {                                              \
    uint32_t _m = (addr); uint32_t _p = (parity); uint32_t _d;                    \
    asm volatile("{ .reg .pred p; mbarrier.try_wait.parity.acquire.cta.shared::cta.b64 p, [%1], %2; selp.b32 %0, 1, 0, p; }" \
        : "=r"(_d) : "r"(_m), "r"(_p) : "memory");                                \
    if (!_d) {                                                                    \
        asm volatile("{ .reg .pred P1; WL%=: mbarrier.try_wait.parity.acquire.cta.shared::cta.b64 P1, [%0], %1, 0x989680; @P1 bra.uni WD%=; bra.uni WL%=; WD%=: }" \
            :: "r"(_m), "r"(_p) : "memory");                                      \
    } } while (0)
__device__ __forceinline__ void ldm4(uint32_t& r0, uint32_t& r1, uint32_t& r2, uint32_t& r3,
                                     uint32_t addr) {
    asm volatile("ldmatrix.sync.aligned.m8n8.x4.shared.b16 {%0,%1,%2,%3}, [%4];"
                 : "=r"(r0), "=r"(r1), "=r"(r2), "=r"(r3) : "r"(addr));
}
__device__ __forceinline__ void ldm2(uint32_t& r0, uint32_t& r1, uint32_t addr) {
    asm volatile("ldmatrix.sync.aligned.m8n8.x2.shared.b16 {%0,%1}, [%2];"
                 : "=r"(r0), "=r"(r1) : "r"(addr));
}
__device__ __forceinline__ void mma16816(float* c, const uint32_t* a, const uint32_t* b) {
    asm volatile(
        "mma.sync.aligned.m16n8k16.row.col.f32.f16.f16.f32 "
        "{%0,%1,%2,%3}, {%4,%5,%6,%7}, {%8,%9}, {%0,%1,%2,%3};"
        : "+f"(c[0]), "+f"(c[1]), "+f"(c[2]), "+f"(c[3])
        : "r"(a[0]), "r"(a[1]), "r"(a[2]), "r"(a[3]), "r"(b[0]), "r"(b[1]));
}

// ============================================================
// Prep: compaction + scaled fp16 hi/lo W packing. grid=EMAX x 256.
// ============================================================
__global__ __launch_bounds__(256) void pack_kernel(const float* __restrict__ W,
                                                   const float* __restrict__ bias,
                                                   const float* __restrict__ alphas,
                                                   int E) {
    __shared__ int   s_eidx[EMAX];
    __shared__ float s_ta[EMAX];
    __shared__ float s_b[EMAX];
    __shared__ int   wtot[8], woff[8];
    __shared__ int   s_na;

    int e = threadIdx.x;
    float ta = 0.f, bi = 0.f;
    int flag = 0;
    if (e < E) {
        ta = truncf(alphas[e]);
        bi = bias[e];
        flag = (ta != 0.f) ? 1 : 0;
    }
    unsigned mask = __ballot_sync(0xffffffffu, flag);
    int lane = e & 31, warp = e >> 5;
    int prefix = __popc(mask & ((1u << lane) - 1u));
    if (lane == 0) wtot[warp] = __popc(mask);
    s_eidx[e] = 0; s_ta[e] = 0.f; s_b[e] = 0.f;
    __syncthreads();
    if (e == 0) {
        int s = 0;
        for (int i = 0; i < 8; i++) { woff[i] = s; s += wtot[i]; }
        s_na = s;
    }
    __syncthreads();
    if (flag) {
        int pos = woff[warp] + prefix;
        s_eidx[pos] = e;
        s_ta[pos] = ta;
        s_b[pos] = bi;
    }
    __syncthreads();

    int na = s_na;
    if (blockIdx.x == 0) {
        g_ta[e]     = s_ta[e];
        g_bias_s[e] = s_b[e] * B_SCALE;
        if (e == 0) {
            g_nactive = na;
            int np = (na + EPP - 1) / EPP;
            if (np < 1) np = 1;
            g_npass = np;
        }
    }

    int p = blockIdx.x, t = threadIdx.x;
    if (p < na) {
        int src = s_eidx[p];
        float2 v = *reinterpret_cast<const float2*>(W + (size_t)src * FDIM + 2 * t);
        float s0 = v.x * W_SCALE, s1 = v.y * W_SCALE;
        __half h0 = __float2half_rn(s0);
        __half h1 = __float2half_rn(s1);
        __half l0 = __float2half_rn(s0 - __half2float(h0));
        __half l1 = __float2half_rn(s1 - __half2float(h1));
        *reinterpret_cast<__half2*>(g_Wh + (size_t)p * FDIM + 2 * t) = __halves2half2(h0, h1);
        *reinterpret_cast<__half2*>(g_Wl + (size_t)p * FDIM + 2 * t) = __halves2half2(l0, l1);
    } else {
        __half2 z = __floats2half2_rn(0.f, 0.f);
        *reinterpret_cast<__half2*>(g_Wh + (size_t)p * FDIM + 2 * t) = z;
        *reinterpret_cast<__half2*>(g_Wl + (size_t)p * FDIM + 2 * t) = z;
    }
}

// ============================================================
// Main: warp-specialized. 64 rows/CTA, 2 CTAs/SM.
// Warps 0-3: consumers (2M x 2N, striped n-tiles tId = nwarp + 2*j).
// Warps 4-7: producers (x LDG->cvt->STS, W cp.async) via 2-stage mbarrier ring.
// ============================================================
#define STR 72
#define XTILE_B 9216                    // 64 * 72 * 2
#define WTILE_B 13824                   // 96 * 72 * 2
#define STAGE_B (2 * XTILE_B + 2 * WTILE_B)   // 46080
#define OFF_STAGE0 0
#define OFF_STAGE1 STAGE_B
#define SOFF_XH 0
#define SOFF_XL XTILE_B
#define SOFF_WH (2 * XTILE_B)
#define SOFF_WL (2 * XTILE_B + WTILE_B)
#define OFF_VOTES (2 * STAGE_B)
#define OFF_SBIAS (OFF_VOTES + 256)
#define OFF_STA   (OFF_SBIAS + 512)
#define OFF_MBAR  (OFF_STA + 512)       // full0, full1, empty0, empty1 (8B each)
#define SMEM_BYTES (OFF_MBAR + 64)

__global__ __launch_bounds__(256, 2) void main_kernel(const float* __restrict__ x,
                                                      float* __restrict__ out,
                                                      int N) {
    extern __shared__ char sm[];
    uint32_t sb = smem_u32(sm);
    float* votes = reinterpret_cast<float*>(sm + OFF_VOTES);
    float* sbias = reinterpret_cast<float*>(sm + OFF_SBIAS);
    float* sta   = reinterpret_cast<float*>(sm + OFF_STA);

    const int tid = threadIdx.x, lane = tid & 31, w = tid >> 5;
    const int rowBase = blockIdx.x * 64;
    const int na = g_nactive, npass = g_npass;

    const uint32_t stageB[2] = { sb + OFF_STAGE0, sb + OFF_STAGE1 };
    const uint32_t fullM[2]  = { sb + OFF_MBAR + 0,  sb + OFF_MBAR + 8 };
    const uint32_t emptyM[2] = { sb + OFF_MBAR + 16, sb + OFF_MBAR + 24 };

    if (tid == 0) {
        MBAR_INIT(fullM[0], 256); MBAR_INIT(fullM[1], 256);
        MBAR_INIT(emptyM[0], 128); MBAR_INIT(emptyM[1], 128);
    }
    if (tid < 64) votes[tid] = 0.f;
    __syncthreads();   // mbarriers + votes visible to everyone

    if (w >= 4) {
        // ===================== PRODUCERS (warps 4-7) =====================
        const int plane = tid - 128;          // 0..127
        const int c4 = plane & 15, rg = plane >> 4;
        int cnt = 0;
        for (int pass = 0; pass < npass; pass++) {
            int pact = na - pass * EPP;
            if (pact > EPP) pact = EPP;
            if (pact < 0) pact = 0;
            const int pactR = (pact + 7) & ~7;
            for (int kc = 0; kc < 8; kc++) {
                const int stage = cnt & 1;
                const int pe = ((cnt >> 1) & 1) ^ 1;
                // stage x in regs BEFORE waiting (pure register work)
                float4 xs[8];
                const float* xp = x + (size_t)rowBase * FDIM + kc * 64 + c4 * 4;
#pragma unroll
                for (int i = 0; i < 8; i++)
                    xs[i] = *reinterpret_cast<const float4*>(xp + (size_t)(i * 8 + rg) * FDIM);

                MBAR_WAIT(emptyM[stage], pe);

                // W prefetch into stage (hi+lo), async -> arrives on fullM (noinc)
                const uint32_t wh = stageB[stage] + SOFF_WH;
                const uint32_t wl = stageB[stage] + SOFF_WL;
#pragma unroll
                for (int jj = 0; jj < 6; jj++) {
                    int unit = plane + jj * 128;   // 0..767
                    int u8 = unit & 7, r = unit >> 3;   // r 0..95
                    if (r < pactR) {
                        size_t go = (size_t)(pass * EPP + r) * FDIM + kc * 64 + u8 * 8;
                        cpa16(wh + (uint32_t)(r * STR + u8 * 8) * 2, g_Wh + go);
                        cpa16(wl + (uint32_t)(r * STR + u8 * 8) * 2, g_Wl + go);
                    }
                }
                cpa_mbar_arrive_noinc(fullM[stage]);

                // convert + STS x (hi+lo)
                const uint32_t xh = stageB[stage] + SOFF_XH;
                const uint32_t xl = stageB[stage] + SOFF_XL;
#pragma unroll
                for (int i = 0; i < 8; i++) {
                    int row = i * 8 + rg;
                    float s0 = xs[i].x * X_SCALE, s1 = xs[i].y * X_SCALE;
                    float s2 = xs[i].z * X_SCALE, s3 = xs[i].w * X_SCALE;
                    __half2 h01 = __floats2half2_rn(s0, s1);
                    __half2 h23 = __floats2half2_rn(s2, s3);
                    __half2 l01 = __floats2half2_rn(s0 - __low2float(h01), s1 - __high2float(h01));
                    __half2 l23 = __floats2half2_rn(s2 - __low2float(h23), s3 - __high2float(h23));
                    uint32_t ah = xh + (uint32_t)(row * STR + c4 * 4) * 2;
                    uint32_t al = xl + (uint32_t)(row * STR + c4 * 4) * 2;
                    asm volatile("st.shared.v2.b32 [%0], {%1,%2};"
                                 :: "r"(ah), "r"(*reinterpret_cast<uint32_t*>(&h01)),
                                    "r"(*reinterpret_cast<uint32_t*>(&h23)) : "memory");
                    asm volatile("st.shared.v2.b32 [%0], {%1,%2};"
                                 :: "r"(al), "r"(*reinterpret_cast<uint32_t*>(&l01)),
                                    "r"(*reinterpret_cast<uint32_t*>(&l23)) : "memory");
                }
                MBAR_ARRIVE(fullM[stage]);
                cnt++;
            }
        }
    } else {
        // ===================== CONSUMERS (warps 0-3) =====================
        const int l8 = lane & 7, grp = lane >> 3;
        const int l4 = lane >> 2, lm = lane & 3;
        const int mwarp = w & 1, nwarp = w >> 1;
        const int mbase = mwarp * 32;
        int cnt = 0;
        for (int pass = 0; pass < npass; pass++) {
            if (tid < EPP) {
                int e = pass * EPP + tid;
                sbias[tid] = g_bias_s[e];
                sta[tid]   = g_ta[e];
            }
            asm volatile("bar.sync 1, 128;" ::: "memory");
            int pact = na - pass * EPP;
            if (pact > EPP) pact = EPP;
            if (pact < 0) pact = 0;

            float c[2][6][4];
#pragma unroll
            for (int mi = 0; mi < 2; mi++)
#pragma unroll
                for (int j = 0; j < 6; j++)
#pragma unroll
                    for (int q = 0; q < 4; q++) c[mi][j][q] = 0.f;

            for (int kc = 0; kc < 8; kc++) {
                const int stage = cnt & 1;
                MBAR_WAIT(fullM[stage], (cnt >> 1) & 1);
                const uint32_t xh = stageB[stage] + SOFF_XH;
                const uint32_t xl = stageB[stage] + SOFF_XL;
                const uint32_t wh = stageB[stage] + SOFF_WH;
                const uint32_t wl = stageB[stage] + SOFF_WL;
#pragma unroll
                for (int ks = 0; ks < 4; ks++) {
                    const int k0 = ks * 16;
                    uint32_t ah[2][4], al[2][4];
#pragma unroll
                    for (int mi = 0; mi < 2; mi++) {
                        int row = mbase + mi * 16 + (grp & 1) * 8 + l8;
                        int ko = k0 + (grp >> 1) * 8;
                        ldm4(ah[mi][0], ah[mi][1], ah[mi][2], ah[mi][3],
                             xh + (uint32_t)(row * STR + ko) * 2);
                        ldm4(al[mi][0], al[mi][1], al[mi][2], al[mi][3],
                             xl + (uint32_t)(row * STR + ko) * 2);
                    }
                    uint32_t bh[6][2], bl[6][2];
#pragma unroll
                    for (int j = 0; j < 6; j++) {
                        int tId = nwarp + 2 * j;
                        if (tId * 8 < pact) {
                            uint32_t off = (uint32_t)((tId * 8 + l8) * STR + k0 + (grp & 1) * 8) * 2;
                            ldm2(bh[j][0], bh[j][1], wh + off);
                            ldm2(bl[j][0], bl[j][1], wl + off);
                        }
                    }
                    // term-major: hh, hl, lh
#pragma unroll
                    for (int j = 0; j < 6; j++)
                        if ((nwarp + 2 * j) * 8 < pact) {
                            mma16816(c[0][j], ah[0], bh[j]);
                            mma16816(c[1][j], ah[1], bh[j]);
                        }
#pragma unroll
                    for (int j = 0; j < 6; j++)
                        if ((nwarp + 2 * j) * 8 < pact) {
                            mma16816(c[0][j], ah[0], bl[j]);
                            mma16816(c[1][j], ah[1], bl[j]);
                        }
#pragma unroll
                    for (int j = 0; j < 6; j++)
                        if ((nwarp + 2 * j) * 8 < pact) {
                            mma16816(c[0][j], al[0], bh[j]);
                            mma16816(c[1][j], al[1], bh[j]);
                        }
                }
                MBAR_ARRIVE(emptyM[stage]);
                cnt++;
            }

            // ---- epilogue: threshold + weighted vote ----
            float acc[2][2] = {{0.f, 0.f}, {0.f, 0.f}};
#pragma unroll
            for (int mi = 0; mi < 2; mi++)
#pragma unroll
                for (int j = 0; j < 6; j++) {
                    int tId = nwarp + 2 * j;
                    if (tId * 8 >= pact) continue;
                    int lc = tId * 8 + 2 * lm;
                    float b0 = sbias[lc], b1 = sbias[lc + 1];
                    float t0 = sta[lc],   t1 = sta[lc + 1];
                    if (c[mi][j][0] + b0 > 0.f) acc[mi][0] += t0;
                    if (c[mi][j][1] + b1 > 0.f) acc[mi][0] += t1;
                    if (c[mi][j][2] + b0 > 0.f) acc[mi][1] += t0;
                    if (c[mi][j][3] + b1 > 0.f) acc[mi][1] += t1;
                }
#pragma unroll
            for (int mi = 0; mi < 2; mi++) {
                if (acc[mi][0] != 0.f) atomicAdd(&votes[mbase + mi * 16 + l4], acc[mi][0]);
                if (acc[mi][1] != 0.f) atomicAdd(&votes[mbase + mi * 16 + l4 + 8], acc[mi][1]);
            }
            asm volatile("bar.sync 1, 128;" ::: "memory");
        }

        if (tid < 64) {
            int r = rowBase + tid;
            if (r < N) {
                float v = votes[tid];
                out[r] = (v > 0.f) ? 1.f : ((v < 0.f) ? -1.f : 0.f);
            }
        }
    }
}

// ============================================================
// Launch
// ============================================================
extern "C" void kernel_launch(void* const* d_in, const int* in_sizes, int n_in,
                              void* d_out, int out_size) {
    const float* x      = (const float*)d_in[0];
    const float* W      = (const float*)d_in[1];
    const float* b      = (const float*)d_in[2];
    const float* alphas = (const float*)d_in[3];
    float* out = (float*)d_out;

    int E = in_sizes[2];   // 256
    int N = out_size;      // 131072

    cudaFuncSetAttribute(main_kernel, cudaFuncAttributeMaxDynamicSharedMemorySize,
                         SMEM_BYTES);

    pack_kernel<<<EMAX, 256>>>(W, b, alphas, E);
    int grid = (N + 63) / 64;
    main_kernel<<<grid, 256, SMEM_BYTES>>>(x, out, N);
}